// round 15
// baseline (speedup 1.0000x reference)
#include <cuda_runtime.h>
#include <cuda_fp16.h>
#include <math.h>

#define B_ 2
#define T_ 8
#define HH_ 48
#define WW_ 48
#define D_ 64
#define DH_ 16
#define NH_ 4
#define M_ 32
#define FFD_ 256
#define HW_ (HH_*WW_)
#define THW_ (T_*HW_)
#define S_ THW_
#define N_ (B_*S_)
#define CHUNK_ 64
#define NCHBH_ (S_/CHUNK_)     // 288
#define NCH_ (B_*NH_*NCHBH_)   // 2304
#define CSZ_ (M_*DH_+M_)       // 544
#define SEG_ 16
#define NSEG_ (NCHBH_/SEG_)    // 18
#define RATIO_ 0.17677669529663687f

typedef unsigned long long ull;
__device__ __forceinline__ ull ffma2(ull a, ull b, ull c) {
    ull d; asm("fma.rn.f32x2 %0, %1, %2, %3;" : "=l"(d) : "l"(a), "l"(b), "l"(c));
    return d;
}
__device__ __forceinline__ ull pk2(float lo, float hi) {
    ull r; asm("mov.b64 %0, {%1, %2};" : "=l"(r) : "f"(lo), "f"(hi)); return r;
}
__device__ __forceinline__ float2 up2(ull v) {
    float2 r; asm("mov.b64 {%0, %1}, %2;" : "=f"(r.x), "=f"(r.y) : "l"(v)); return r;
}

__device__ float g_tokens[B_*S_*D_];
__device__ float g_qp[B_*NH_*S_*M_];
__device__ float g_kp[B_*NH_*S_*M_];
__device__ float g_v [B_*NH_*S_*DH_];
__device__ float g_chunk[NCH_*CSZ_];
__device__ float g_seg[B_*NH_*NSEG_*CSZ_];
__device__ float g_accum[B_];
__device__ unsigned g_kmax_bits;

__device__ __forceinline__ unsigned enc_max(float f) {
    unsigned b = __float_as_uint(f);
    return (b & 0x80000000u) ? ~b : (b | 0x80000000u);
}
__device__ __forceinline__ float dec_max(unsigned u) {
    return __uint_as_float((u & 0x80000000u) ? (u & 0x7fffffffu) : ~u);
}

__global__ void k_init() {
    if (threadIdx.x == 0) g_kmax_bits = 0u;
    if (threadIdx.x < B_) g_accum[threadIdx.x] = 0.f;
}

// preproc(conv1x1+softplus, writes g_tokens) + LN1 + QKV (FFMA2) + FAVOR+ features
__global__ void __launch_bounds__(256) k_qkv(
        const float* __restrict__ x, const float* __restrict__ pw,
        const float* __restrict__ pb,
        const float* __restrict__ ln_g, const float* __restrict__ ln_b,
        const float* __restrict__ wq, const float* __restrict__ wk,
        const float* __restrict__ wv, const float* __restrict__ proj) {
    __shared__ float sht[64][34];
    __shared__ float sqv[32][68], skv[32][68];
    __shared__ float smu[32], sinv[32], sproj[512];
    int tid = threadIdx.x;
    int n0 = blockIdx.x*32, b = n0 / S_;
    if (tid < 128) *(float4*)(sproj + tid*4) = *(const float4*)(proj + tid*4);
    {
        int f0 = (n0 - b*S_)*64;
        int dd = f0 / THW_, p0 = f0 - dd*THW_;
        const float* xb = x + (size_t)b*3*THW_ + p0;
        float w0 = pw[dd*3], w1 = pw[dd*3+1], w2 = pw[dd*3+2], bb = pb[dd];
        for (int f = tid; f < 512; f += 256) {
            int j4 = f*4;
            float4 c0 = *(const float4*)(xb + j4);
            float4 c1 = *(const float4*)(xb + THW_ + j4);
            float4 c2 = *(const float4*)(xb + 2*THW_ + j4);
            float4 o; float v;
            v = bb + w0*c0.x + w1*c1.x + w2*c2.x; o.x = (v>20.f)?v:__logf(1.f+__expf(v));
            v = bb + w0*c0.y + w1*c1.y + w2*c2.y; o.y = (v>20.f)?v:__logf(1.f+__expf(v));
            v = bb + w0*c0.z + w1*c1.z + w2*c2.z; o.z = (v>20.f)?v:__logf(1.f+__expf(v));
            v = bb + w0*c0.w + w1*c1.w + w2*c2.w; o.w = (v>20.f)?v:__logf(1.f+__expf(v));
            *(float4*)(g_tokens + (size_t)n0*64 + j4) = o;
            int t = j4 >> 6, d = j4 & 63;
            sht[d][t]=o.x; sht[d+1][t]=o.y; sht[d+2][t]=o.z; sht[d+3][t]=o.w;
        }
    }
    __syncthreads();
    if (tid < 32) {
        float s = 0.f, ss = 0.f;
        #pragma unroll 8
        for (int d = 0; d < 64; d++) { float v = sht[d][tid]; s += v; ss += v*v; }
        float mu = s*(1.f/64.f);
        smu[tid] = mu;
        sinv[tid] = rsqrtf(ss*(1.f/64.f) - mu*mu + 1e-5f);
    }
    __syncthreads();
    for (int e = tid; e < 2048; e += 256) {
        int d = e >> 5, t = e & 31;
        sht[d][t] = (sht[d][t] - smu[t])*sinv[t]*ln_g[d] + ln_b[d];
    }
    __syncthreads();
    int cg = tid & 63, tg = tid >> 6;
    int c0 = cg*4, t0 = tg*8;
    const float* wptr = (c0 < 64) ? wq + c0 : (c0 < 128) ? wk + (c0-64)
                       : (c0 < 192) ? wv + (c0-128) : wq;
    ull acc[4][4];
    #pragma unroll
    for (int tp = 0; tp < 4; tp++)
        #pragma unroll
        for (int c = 0; c < 4; c++) acc[tp][c] = 0ull;
    #pragma unroll 4
    for (int d = 0; d < 64; d++) {
        float4 w = *(const float4*)(wptr + d*64);
        ull wb0 = pk2(w.x,w.x), wb1 = pk2(w.y,w.y), wb2 = pk2(w.z,w.z), wb3 = pk2(w.w,w.w);
        #pragma unroll
        for (int tp = 0; tp < 4; tp++) {
            ull hp = *(const ull*)&sht[d][t0 + 2*tp];
            acc[tp][0] = ffma2(hp, wb0, acc[tp][0]);
            acc[tp][1] = ffma2(hp, wb1, acc[tp][1]);
            acc[tp][2] = ffma2(hp, wb2, acc[tp][2]);
            acc[tp][3] = ffma2(hp, wb3, acc[tp][3]);
        }
    }
    #pragma unroll
    for (int tp = 0; tp < 4; tp++) {
        float2 p0 = up2(acc[tp][0]), p1 = up2(acc[tp][1]);
        float2 p2 = up2(acc[tp][2]), p3 = up2(acc[tp][3]);
        int t = t0 + 2*tp;
        if (c0 < 64) {
            *(float4*)(&sqv[t][c0])   = make_float4(p0.x,p1.x,p2.x,p3.x);
            *(float4*)(&sqv[t+1][c0]) = make_float4(p0.y,p1.y,p2.y,p3.y);
        } else if (c0 < 128) {
            *(float4*)(&skv[t][c0-64])   = make_float4(p0.x,p1.x,p2.x,p3.x);
            *(float4*)(&skv[t+1][c0-64]) = make_float4(p0.y,p1.y,p2.y,p3.y);
        } else if (c0 < 192) {
            int cv = c0-128, hh = cv >> 4, off = cv & 15;
            int s = n0 + t - b*S_;
            *(float4*)(g_v + ((size_t)(b*NH_+hh)*S_ + s)*DH_ + off) =
                make_float4(p0.x,p1.x,p2.x,p3.x);
            *(float4*)(g_v + ((size_t)(b*NH_+hh)*S_ + s+1)*DH_ + off) =
                make_float4(p0.y,p1.y,p2.y,p3.y);
        }
    }
    __syncthreads();
    {
        int t = tid >> 3, h = (tid >> 1) & 3, half = tid & 1;
        int s = n0 + t - b*S_;
        float qh[16], kh[16];
        #pragma unroll
        for (int d = 0; d < 16; d++) { qh[d] = sqv[t][h*16+d]; kh[d] = skv[t][h*16+d]; }
        float dgq = 0.f, dgk = 0.f;
        #pragma unroll
        for (int d = 0; d < 16; d++) { dgq += qh[d]*qh[d]; dgk += kh[d]*kh[d]; }
        dgq *= 0.125f; dgk *= 0.125f;
        float dq[16];
        float mxq = -1e30f, mxk = -1e30f;
        size_t base = ((size_t)(b*NH_+h)*S_ + s)*M_ + half*16;
        #pragma unroll
        for (int m4 = 0; m4 < 16; m4 += 4) {
            float kk[4];
            #pragma unroll
            for (int mm = 0; mm < 4; mm++) {
                const float* pr = sproj + (half*16 + m4 + mm)*16;
                float aq = 0.f, ak = 0.f;
                #pragma unroll
                for (int d = 0; d < 16; d++) { aq += qh[d]*pr[d]; ak += kh[d]*pr[d]; }
                float dqv = 0.5f*aq, dkv = 0.5f*ak;
                dq[m4+mm] = dqv;
                mxq = fmaxf(mxq, dqv); mxk = fmaxf(mxk, dkv);
                kk[mm] = dkv - dgk;
            }
            *(float4*)(g_kp + base + m4) = make_float4(kk[0],kk[1],kk[2],kk[3]);
        }
        mxq = fmaxf(mxq, __shfl_xor_sync(~0u, mxq, 1));
        float mk = mxk;
        #pragma unroll
        for (int o = 16; o; o >>= 1) mk = fmaxf(mk, __shfl_xor_sync(~0u, mk, o));
        if ((tid & 31) == 0) atomicMax(&g_kmax_bits, enc_max(mk));
        #pragma unroll
        for (int m4 = 0; m4 < 16; m4 += 4) {
            float4 qo;
            qo.x = RATIO_*(__expf(dq[m4]   - dgq - mxq) + 1e-4f);
            qo.y = RATIO_*(__expf(dq[m4+1] - dgq - mxq) + 1e-4f);
            qo.z = RATIO_*(__expf(dq[m4+2] - dgq - mxq) + 1e-4f);
            qo.w = RATIO_*(__expf(dq[m4+3] - dgq - mxq) + 1e-4f);
            *(float4*)(g_qp + base + m4) = qo;
        }
    }
}

// per-chunk K / K^T V sums (exp in smem only). 2 chunks/block.
__global__ void __launch_bounds__(256) k_chunksum() {
    __shared__ float skp[2][64][33];
    __shared__ float sv [2][64][16];
    int tid = threadIdx.x, half = tid >> 7, lt = tid & 127;
    int ch = blockIdx.x*2 + half;
    float kmax = dec_max(g_kmax_bits);
    size_t kbase = (size_t)ch*CHUNK_*M_;
    size_t vbase = (size_t)ch*CHUNK_*DH_;
    for (int f = lt; f < 512; f += 128) {
        float4 a = *(const float4*)(g_kp + kbase + (f<<2));
        a.x = RATIO_*(__expf(a.x-kmax)+1e-4f); a.y = RATIO_*(__expf(a.y-kmax)+1e-4f);
        a.z = RATIO_*(__expf(a.z-kmax)+1e-4f); a.w = RATIO_*(__expf(a.w-kmax)+1e-4f);
        int s = f >> 3, m0 = (f & 7) << 2;
        skp[half][s][m0]=a.x; skp[half][s][m0+1]=a.y;
        skp[half][s][m0+2]=a.z; skp[half][s][m0+3]=a.w;
    }
    for (int f = lt; f < 256; f += 128)
        *(float4*)(&sv[half][f>>2][(f&3)<<2]) = *(const float4*)(g_v + vbase + (f<<2));
    __syncthreads();
    int m0 = (lt >> 3)*2, d0 = (lt & 7)*2;
    ull a0 = 0ull, a1 = 0ull;
    #pragma unroll 8
    for (int s = 0; s < 64; s++) {
        ull vp = *(const ull*)&sv[half][s][d0];
        a0 = ffma2(pk2(skp[half][s][m0],   skp[half][s][m0]),   vp, a0);
        a1 = ffma2(pk2(skp[half][s][m0+1], skp[half][s][m0+1]), vp, a1);
    }
    float2 r0 = up2(a0), r1 = up2(a1);
    size_t cb = (size_t)ch*CSZ_;
    g_chunk[cb + m0*16 + d0]   = r0.x; g_chunk[cb + m0*16 + d0+1]   = r0.y;
    g_chunk[cb + (m0+1)*16+d0] = r1.x; g_chunk[cb + (m0+1)*16+d0+1] = r1.y;
    if (lt < 32) {
        float s2 = 0.f;
        #pragma unroll 8
        for (int s = 0; s < 64; s++) s2 += skp[half][s][lt];
        g_chunk[cb + 512 + lt] = s2;
    }
}

// segment sums (float4)
__global__ void k_scanA() {
    int e4 = threadIdx.x*4;
    int bh = blockIdx.x / NSEG_, seg = blockIdx.x % NSEG_;
    int c0 = seg*SEG_;
    float4 s = make_float4(0,0,0,0);
    for (int ci = 0; ci < SEG_; ci++) {
        float4 v = *(const float4*)(g_chunk + ((size_t)(bh*NCHBH_ + c0 + ci))*CSZ_ + e4);
        s.x += v.x; s.y += v.y; s.z += v.z; s.w += v.w;
    }
    *(float4*)(g_seg + (size_t)blockIdx.x*CSZ_ + e4) = s;
}
// exclusive prefix within segment, offset by prior segment sums (float4)
__global__ void k_scanC() {
    int e4 = threadIdx.x*4;
    int bh = blockIdx.x / NSEG_, seg = blockIdx.x % NSEG_;
    float4 run = make_float4(0,0,0,0);
    for (int g = 0; g < seg; g++) {
        float4 v = *(const float4*)(g_seg + (size_t)(bh*NSEG_+g)*CSZ_ + e4);
        run.x += v.x; run.y += v.y; run.z += v.z; run.w += v.w;
    }
    int c0 = seg*SEG_;
    for (int ci = 0; ci < SEG_; ci++) {
        float* p = g_chunk + ((size_t)(bh*NCHBH_ + c0 + ci))*CSZ_ + e4;
        float4 v = *(const float4*)p;
        *(float4*)p = run;
        run.x += v.x; run.y += v.y; run.z += v.z; run.w += v.w;
    }
}

// intra-chunk causal attention (exp on load, FFMA2, fp16 A-matrix)
__global__ void __launch_bounds__(256) k_intra() {
    __shared__ float sq [64][33];
    __shared__ float skt[32][66];
    __shared__ float sv [64][16];
    __shared__ __half sA[64][72];
    __shared__ float sctx[32][16], sk0[32], rden[64];
    int tid = threadIdx.x, ch = blockIdx.x;
    float kmax = dec_max(g_kmax_bits);
    size_t fbase = (size_t)ch*CHUNK_*M_;
    size_t vbase = (size_t)ch*CHUNK_*DH_;
    size_t cb = (size_t)ch*CSZ_;
    for (int f = tid; f < 512; f += 256) {
        int s = f >> 3, m0 = (f & 7) << 2;
        float4 a = *(const float4*)(g_qp + fbase + (f<<2));
        sq[s][m0]=a.x; sq[s][m0+1]=a.y; sq[s][m0+2]=a.z; sq[s][m0+3]=a.w;
        float4 b = *(const float4*)(g_kp + fbase + (f<<2));
        skt[m0][s]   = RATIO_*(__expf(b.x-kmax)+1e-4f);
        skt[m0+1][s] = RATIO_*(__expf(b.y-kmax)+1e-4f);
        skt[m0+2][s] = RATIO_*(__expf(b.z-kmax)+1e-4f);
        skt[m0+3][s] = RATIO_*(__expf(b.w-kmax)+1e-4f);
    }
    *(float4*)(&sv[tid>>2][(tid&3)<<2]) = *(const float4*)(g_v + vbase + (tid<<2));
    if (tid < 128)
        *(float4*)(&sctx[tid>>2][(tid&3)<<2]) = *(const float4*)(g_chunk + cb + (tid<<2));
    if (tid < 8) *(float4*)(sk0 + tid*4) = *(const float4*)(g_chunk + cb + 512 + tid*4);
    __syncthreads();
    {
        int i0 = (tid >> 4)*4, j0 = (tid & 15)*4;
        if (j0 <= i0 + 3) {
            ull a[4][2];
            #pragma unroll
            for (int r = 0; r < 4; r++) { a[r][0]=0ull; a[r][1]=0ull; }
            #pragma unroll 4
            for (int m = 0; m < 32; m++) {
                ull kp01 = *(const ull*)&skt[m][j0];
                ull kp23 = *(const ull*)&skt[m][j0+2];
                #pragma unroll
                for (int r = 0; r < 4; r++) {
                    ull qb = pk2(sq[i0+r][m], sq[i0+r][m]);
                    a[r][0] = ffma2(qb, kp01, a[r][0]);
                    a[r][1] = ffma2(qb, kp23, a[r][1]);
                }
            }
            #pragma unroll
            for (int r = 0; r < 4; r++) {
                float2 p0 = up2(a[r][0]), p1 = up2(a[r][1]);
                *(__half2*)&sA[i0+r][j0]   = __floats2half2_rn(p0.x, p0.y);
                *(__half2*)&sA[i0+r][j0+2] = __floats2half2_rn(p1.x, p1.y);
            }
        }
    }
    __syncthreads();
    if (tid < 64) {
        int i = tid;
        float den = 0.f;
        #pragma unroll 8
        for (int m = 0; m < 32; m++) den += sq[i][m]*sk0[m];
        for (int j = 0; j <= i; j++) den += __half2float(sA[i][j]);
        rden[i] = 1.f/den;
    }
    __syncthreads();
    {
        int i = tid >> 2, d0 = (tid & 3) << 2;
        ull acc0 = 0ull, acc1 = 0ull;
        #pragma unroll 8
        for (int m = 0; m < 32; m++) {
            ull qb = pk2(sq[i][m], sq[i][m]);
            acc0 = ffma2(qb, *(const ull*)&sctx[m][d0],   acc0);
            acc1 = ffma2(qb, *(const ull*)&sctx[m][d0+2], acc1);
        }
        for (int j = 0; j <= i; j++) {
            float av = __half2float(sA[i][j]);
            ull ab = pk2(av, av);
            acc0 = ffma2(ab, *(const ull*)&sv[j][d0],   acc0);
            acc1 = ffma2(ab, *(const ull*)&sv[j][d0+2], acc1);
        }
        float2 p0 = up2(acc0), p1 = up2(acc1);
        float r = rden[i];
        *(float4*)(g_v + vbase + i*16 + d0) = make_float4(p0.x*r,p0.y*r,p1.x*r,p1.y*r);
    }
}

// fused: o-proj + residual + LN2 + FF (gelu, fp16 activations) + residual
// sa and sht share one buffer (sa dead after o-proj, sht written after sync)
__global__ void __launch_bounds__(256) k_post(
        const float* __restrict__ wo, const float* __restrict__ bo,
        const float* __restrict__ g2, const float* __restrict__ b2ln,
        const float* __restrict__ w1, const float* __restrict__ b1,
        const float* __restrict__ w2, const float* __restrict__ b2) {
    __shared__ float sbuf[32*68];      // phase1: sa[t][c] (t*68+c); phase2+: sht[d][t] (d*34+t)
    __shared__ float st [32][68];
    __shared__ __half2 sg2[32][132];
    __shared__ float smu[32], sinv[32];
    #define SA_(t,c) sbuf[(t)*68+(c)]
    #define SHT_(d,t) sbuf[(d)*34+(t)]
    int tid = threadIdx.x;
    int n0 = blockIdx.x*32, b = n0 / S_;
    for (int f = tid; f < 512; f += 256) {
        int t = f >> 4, c4 = f & 15;
        int s = n0 + t - b*S_;
        int hh = c4 >> 2, off = (c4 & 3) << 2;
        *(float4*)(&SA_(t, c4*4)) =
            *(const float4*)(g_v + ((size_t)(b*NH_+hh)*S_ + s)*DH_ + off);
        int d4 = c4 << 2;
        *(float4*)(&st[t][d4]) = *(const float4*)(g_tokens + (size_t)(n0+t)*64 + d4);
    }
    __syncthreads();
    {
        int c0 = (tid & 15)*4, t0 = (tid >> 4)*2;
        ull a00=0ull,a01=0ull,a10=0ull,a11=0ull;
        #pragma unroll 4
        for (int i = 0; i < 64; i++) {
            float4 w = *(const float4*)(wo + i*64 + c0);
            ull wlo = pk2(w.x,w.y), whi = pk2(w.z,w.w);
            ull h0 = pk2(SA_(t0,i), SA_(t0,i));
            ull h1 = pk2(SA_(t0+1,i), SA_(t0+1,i));
            a00 = ffma2(h0, wlo, a00); a01 = ffma2(h0, whi, a01);
            a10 = ffma2(h1, wlo, a10); a11 = ffma2(h1, whi, a11);
        }
        float4 bv = *(const float4*)(bo + c0);
        float2 p0 = up2(a00), p1 = up2(a01), p2 = up2(a10), p3 = up2(a11);
        float4 r = *(float4*)(&st[t0][c0]);
        r.x += p0.x+bv.x; r.y += p0.y+bv.y; r.z += p1.x+bv.z; r.w += p1.y+bv.w;
        *(float4*)(&st[t0][c0]) = r;
        float4 r2 = *(float4*)(&st[t0+1][c0]);
        r2.x += p2.x+bv.x; r2.y += p2.y+bv.y; r2.z += p3.x+bv.z; r2.w += p3.y+bv.w;
        *(float4*)(&st[t0+1][c0]) = r2;
    }
    __syncthreads();
    if (tid < 32) {
        float s = 0.f, ss = 0.f;
        #pragma unroll 8
        for (int d = 0; d < 64; d++) { float v = st[tid][d]; s += v; ss += v*v; }
        float mu = s*(1.f/64.f);
        smu[tid] = mu;
        sinv[tid] = rsqrtf(ss*(1.f/64.f) - mu*mu + 1e-5f);
    }
    __syncthreads();
    for (int e = tid; e < 2048; e += 256) {
        int t = e >> 6, d = e & 63;
        SHT_(d,t) = (st[t][d] - smu[t])*sinv[t]*g2[d] + b2ln[d];
    }
    __syncthreads();
    {   // FF1 (token-pair packed), gelu -> fp16
        int c0 = (tid & 63)*4, t0 = (tid >> 6)*8;
        ull acc[4][4];
        #pragma unroll
        for (int tp = 0; tp < 4; tp++)
            #pragma unroll
            for (int c = 0; c < 4; c++) acc[tp][c] = 0ull;
        #pragma unroll 4
        for (int d = 0; d < 64; d++) {
            float4 w = *(const float4*)(w1 + d*256 + c0);
            ull wb0 = pk2(w.x,w.x), wb1 = pk2(w.y,w.y), wb2 = pk2(w.z,w.z), wb3 = pk2(w.w,w.w);
            #pragma unroll
            for (int tp = 0; tp < 4; tp++) {
                ull hp = *(const ull*)&SHT_(d, t0 + 2*tp);
                acc[tp][0] = ffma2(hp, wb0, acc[tp][0]);
                acc[tp][1] = ffma2(hp, wb1, acc[tp][1]);
                acc[tp][2] = ffma2(hp, wb2, acc[tp][2]);
                acc[tp][3] = ffma2(hp, wb3, acc[tp][3]);
            }
        }
        float4 bv = *(const float4*)(b1 + c0);
        #pragma unroll
        for (int tp = 0; tp < 4; tp++) {
            float2 p0 = up2(acc[tp][0]), p1 = up2(acc[tp][1]);
            float2 p2 = up2(acc[tp][2]), p3 = up2(acc[tp][3]);
            int t = t0 + 2*tp;
            float u; float4 o;
            u = p0.x+bv.x; o.x = 0.5f*u*(1.f+erff(u*0.70710678f));
            u = p1.x+bv.y; o.y = 0.5f*u*(1.f+erff(u*0.70710678f));
            u = p2.x+bv.z; o.z = 0.5f*u*(1.f+erff(u*0.70710678f));
            u = p3.x+bv.w; o.w = 0.5f*u*(1.f+erff(u*0.70710678f));
            sg2[t][(c0>>1)]   = __floats2half2_rn(o.x, o.y);
            sg2[t][(c0>>1)+1] = __floats2half2_rn(o.z, o.w);
            u = p0.y+bv.x; o.x = 0.5f*u*(1.f+erff(u*0.70710678f));
            u = p1.y+bv.y; o.y = 0.5f*u*(1.f+erff(u*0.70710678f));
            u = p2.y+bv.z; o.z = 0.5f*u*(1.f+erff(u*0.70710678f));
            u = p3.y+bv.w; o.w = 0.5f*u*(1.f+erff(u*0.70710678f));
            sg2[t+1][(c0>>1)]   = __floats2half2_rn(o.x, o.y);
            sg2[t+1][(c0>>1)+1] = __floats2half2_rn(o.z, o.w);
        }
    }
    __syncthreads();
    {   // FF2 + residual
        int c0 = (tid & 15)*4, t0 = (tid >> 4)*2;
        ull a00=0ull,a01=0ull,a10=0ull,a11=0ull;
        #pragma unroll 4
        for (int fp = 0; fp < 128; fp++) {
            float2 h0f = __half22float2(sg2[t0][fp]);
            float2 h1f = __half22float2(sg2[t0+1][fp]);
            int f = fp*2;
            float4 wA = *(const float4*)(w2 + f*64 + c0);
            float4 wB = *(const float4*)(w2 + (f+1)*64 + c0);
            ull wloA = pk2(wA.x,wA.y), whiA = pk2(wA.z,wA.w);
            ull wloB = pk2(wB.x,wB.y), whiB = pk2(wB.z,wB.w);
            ull h00 = pk2(h0f.x,h0f.x), h01 = pk2(h0f.y,h0f.y);
            ull h10 = pk2(h1f.x,h1f.x), h11 = pk2(h1f.y,h1f.y);
            a00 = ffma2(h00, wloA, a00); a01 = ffma2(h00, whiA, a01);
            a10 = ffma2(h10, wloA, a10); a11 = ffma2(h10, whiA, a11);
            a00 = ffma2(h01, wloB, a00); a01 = ffma2(h01, whiB, a01);
            a10 = ffma2(h11, wloB, a10); a11 = ffma2(h11, whiB, a11);
        }
        float4 bv = *(const float4*)(b2 + c0);
        float2 p0 = up2(a00), p1 = up2(a01), p2 = up2(a10), p3 = up2(a11);
        float4 r = *(float4*)(&st[t0][c0]);
        r.x += p0.x+bv.x; r.y += p0.y+bv.y; r.z += p1.x+bv.z; r.w += p1.y+bv.w;
        *(float4*)(g_tokens + (size_t)(n0+t0)*64 + c0) = r;
        float4 r2 = *(float4*)(&st[t0+1][c0]);
        r2.x += p2.x+bv.x; r2.y += p2.y+bv.y; r2.z += p3.x+bv.z; r2.w += p3.y+bv.w;
        *(float4*)(g_tokens + (size_t)(n0+t0+1)*64 + c0) = r2;
    }
    #undef SA_
    #undef SHT_
}

// fused readout: mean-over-T + 5x5 conv (pad 2) + spatial sum via clipped tap sums
__global__ void k_read(const float* __restrict__ x, const float* __restrict__ tw) {
    int idx = blockIdx.x*256 + threadIdx.x;
    int hw = idx % HW_;
    int t2 = idx / HW_;
    int c = t2 % (D_+1), b = t2 / (D_+1);
    float v;
    if (c < D_) {
        float acc = 0.f;
        #pragma unroll
        for (int t = 0; t < T_; t++)
            acc += g_tokens[(size_t)b*S_*64 + (size_t)c*THW_ + t*HW_ + hw];
        v = acc*(1.f/T_);
    } else {
        v = x[((size_t)b*3 + 2)*THW_ + hw];
    }
    int y = hw / WW_, xx = hw % WW_;
    int kylo = max(0, y-45), kyhi = min(4, y+2);
    int kxlo = max(0, xx-45), kxhi = min(4, xx+2);
    float w = 0.f;
    for (int ky = kylo; ky <= kyhi; ky++)
        for (int kx = kxlo; kx <= kxhi; kx++)
            w += tw[c*25 + ky*5 + kx];
    float contrib = v*w;
    __shared__ float red[256];
    red[threadIdx.x] = contrib; __syncthreads();
    #pragma unroll
    for (int o = 128; o; o >>= 1) {
        if (threadIdx.x < o) red[threadIdx.x] += red[threadIdx.x + o];
        __syncthreads();
    }
    if (threadIdx.x == 0) atomicAdd(&g_accum[b], red[0]);
}

__global__ void k_final(const float* __restrict__ tb, const float* __restrict__ rw,
                        const float* __restrict__ rb, float* __restrict__ out) {
    int b = threadIdx.x;
    if (b < B_) out[b] = (g_accum[b]*(1.f/HW_) + tb[0])*rw[0] + rb[0];
}

extern "C" void kernel_launch(void* const* d_in, const int* in_sizes, int n_in,
                              void* d_out, int out_size) {
    const float* x    = (const float*)d_in[0];
    const float* prw  = (const float*)d_in[1];
    const float* prb  = (const float*)d_in[2];
    const float* ln1g = (const float*)d_in[3];
    const float* ln1b = (const float*)d_in[4];
    const float* wq   = (const float*)d_in[5];
    const float* wk   = (const float*)d_in[6];
    const float* wv   = (const float*)d_in[7];
    const float* wo   = (const float*)d_in[8];
    const float* bo   = (const float*)d_in[9];
    const float* proj = (const float*)d_in[10];
    const float* ln2g = (const float*)d_in[11];
    const float* ln2b = (const float*)d_in[12];
    const float* w1   = (const float*)d_in[13];
    const float* b1   = (const float*)d_in[14];
    const float* w2   = (const float*)d_in[15];
    const float* b2   = (const float*)d_in[16];
    const float* tw   = (const float*)d_in[17];
    const float* tb   = (const float*)d_in[18];
    const float* rw   = (const float*)d_in[19];
    const float* rb   = (const float*)d_in[20];
    float* out = (float*)d_out;

    k_init<<<1, 32>>>();
    k_qkv<<<N_/32, 256>>>(x, prw, prb, ln1g, ln1b, wq, wk, wv, proj);
    k_chunksum<<<NCH_/2, 256>>>();
    k_scanA<<<B_*NH_*NSEG_, CSZ_/4>>>();
    k_scanC<<<B_*NH_*NSEG_, CSZ_/4>>>();
    k_intra<<<NCH_, 256>>>();
    k_post<<<N_/32, 256>>>(wo, bo, ln2g, ln2b, w1, b1, w2, b2);
    k_read<<<(B_*(D_+1)*HW_)/256, 256>>>(x, tw);
    k_final<<<1, 32>>>(tb, rw, rb, out);
}

// round 16
// speedup vs baseline: 1.0018x; 1.0018x over previous
#include <cuda_runtime.h>
#include <cuda_fp16.h>
#include <math.h>

#define B_ 2
#define T_ 8
#define HH_ 48
#define WW_ 48
#define D_ 64
#define DH_ 16
#define NH_ 4
#define M_ 32
#define FFD_ 256
#define HW_ (HH_*WW_)
#define THW_ (T_*HW_)
#define S_ THW_
#define N_ (B_*S_)
#define CHUNK_ 64
#define NCHBH_ (S_/CHUNK_)     // 288
#define NCH_ (B_*NH_*NCHBH_)   // 2304
#define CSZ_ (M_*DH_+M_)       // 544
#define SEG_ 16
#define NSEG_ (NCHBH_/SEG_)    // 18
#define RATIO_ 0.17677669529663687f

typedef unsigned long long ull;
__device__ __forceinline__ ull ffma2(ull a, ull b, ull c) {
    ull d; asm("fma.rn.f32x2 %0, %1, %2, %3;" : "=l"(d) : "l"(a), "l"(b), "l"(c));
    return d;
}
__device__ __forceinline__ ull pk2(float lo, float hi) {
    ull r; asm("mov.b64 %0, {%1, %2};" : "=l"(r) : "f"(lo), "f"(hi)); return r;
}
__device__ __forceinline__ float2 up2(ull v) {
    float2 r; asm("mov.b64 {%0, %1}, %2;" : "=f"(r.x), "=f"(r.y) : "l"(v)); return r;
}

__device__ float g_tokens[B_*S_*D_];
__device__ __half g_qp[B_*NH_*S_*M_];   // q features, fp16 (values in (0, 0.177])
__device__ float g_kp[B_*NH_*S_*M_];
__device__ float g_v [B_*NH_*S_*DH_];
__device__ float g_chunk[NCH_*CSZ_];
__device__ float g_seg[B_*NH_*NSEG_*CSZ_];
__device__ float g_accum[B_];
__device__ unsigned g_kmax_bits;

__device__ __forceinline__ unsigned enc_max(float f) {
    unsigned b = __float_as_uint(f);
    return (b & 0x80000000u) ? ~b : (b | 0x80000000u);
}
__device__ __forceinline__ float dec_max(unsigned u) {
    return __uint_as_float((u & 0x80000000u) ? (u & 0x7fffffffu) : ~u);
}

__global__ void k_init() {
    if (threadIdx.x == 0) g_kmax_bits = 0u;
    if (threadIdx.x < B_) g_accum[threadIdx.x] = 0.f;
}

// preproc(conv1x1+softplus, writes g_tokens) + LN1 + QKV (FFMA2) + FAVOR+ features
__global__ void __launch_bounds__(256) k_qkv(
        const float* __restrict__ x, const float* __restrict__ pw,
        const float* __restrict__ pb,
        const float* __restrict__ ln_g, const float* __restrict__ ln_b,
        const float* __restrict__ wq, const float* __restrict__ wk,
        const float* __restrict__ wv, const float* __restrict__ proj) {
    __shared__ float sht[64][34];
    __shared__ float sqv[32][68], skv[32][68];
    __shared__ float smu[32], sinv[32], sproj[512];
    int tid = threadIdx.x;
    int n0 = blockIdx.x*32, b = n0 / S_;
    if (tid < 128) *(float4*)(sproj + tid*4) = *(const float4*)(proj + tid*4);
    {
        int f0 = (n0 - b*S_)*64;
        int dd = f0 / THW_, p0 = f0 - dd*THW_;
        const float* xb = x + (size_t)b*3*THW_ + p0;
        float w0 = pw[dd*3], w1 = pw[dd*3+1], w2 = pw[dd*3+2], bb = pb[dd];
        for (int f = tid; f < 512; f += 256) {
            int j4 = f*4;
            float4 c0 = *(const float4*)(xb + j4);
            float4 c1 = *(const float4*)(xb + THW_ + j4);
            float4 c2 = *(const float4*)(xb + 2*THW_ + j4);
            float4 o; float v;
            v = bb + w0*c0.x + w1*c1.x + w2*c2.x; o.x = (v>20.f)?v:__logf(1.f+__expf(v));
            v = bb + w0*c0.y + w1*c1.y + w2*c2.y; o.y = (v>20.f)?v:__logf(1.f+__expf(v));
            v = bb + w0*c0.z + w1*c1.z + w2*c2.z; o.z = (v>20.f)?v:__logf(1.f+__expf(v));
            v = bb + w0*c0.w + w1*c1.w + w2*c2.w; o.w = (v>20.f)?v:__logf(1.f+__expf(v));
            *(float4*)(g_tokens + (size_t)n0*64 + j4) = o;
            int t = j4 >> 6, d = j4 & 63;
            sht[d][t]=o.x; sht[d+1][t]=o.y; sht[d+2][t]=o.z; sht[d+3][t]=o.w;
        }
    }
    __syncthreads();
    if (tid < 32) {
        float s = 0.f, ss = 0.f;
        #pragma unroll 8
        for (int d = 0; d < 64; d++) { float v = sht[d][tid]; s += v; ss += v*v; }
        float mu = s*(1.f/64.f);
        smu[tid] = mu;
        sinv[tid] = rsqrtf(ss*(1.f/64.f) - mu*mu + 1e-5f);
    }
    __syncthreads();
    for (int e = tid; e < 2048; e += 256) {
        int d = e >> 5, t = e & 31;
        sht[d][t] = (sht[d][t] - smu[t])*sinv[t]*ln_g[d] + ln_b[d];
    }
    __syncthreads();
    int cg = tid & 63, tg = tid >> 6;
    int c0 = cg*4, t0 = tg*8;
    const float* wptr = (c0 < 64) ? wq + c0 : (c0 < 128) ? wk + (c0-64)
                       : (c0 < 192) ? wv + (c0-128) : wq;
    ull acc[4][4];
    #pragma unroll
    for (int tp = 0; tp < 4; tp++)
        #pragma unroll
        for (int c = 0; c < 4; c++) acc[tp][c] = 0ull;
    #pragma unroll 4
    for (int d = 0; d < 64; d++) {
        float4 w = *(const float4*)(wptr + d*64);
        ull wb0 = pk2(w.x,w.x), wb1 = pk2(w.y,w.y), wb2 = pk2(w.z,w.z), wb3 = pk2(w.w,w.w);
        #pragma unroll
        for (int tp = 0; tp < 4; tp++) {
            ull hp = *(const ull*)&sht[d][t0 + 2*tp];
            acc[tp][0] = ffma2(hp, wb0, acc[tp][0]);
            acc[tp][1] = ffma2(hp, wb1, acc[tp][1]);
            acc[tp][2] = ffma2(hp, wb2, acc[tp][2]);
            acc[tp][3] = ffma2(hp, wb3, acc[tp][3]);
        }
    }
    #pragma unroll
    for (int tp = 0; tp < 4; tp++) {
        float2 p0 = up2(acc[tp][0]), p1 = up2(acc[tp][1]);
        float2 p2 = up2(acc[tp][2]), p3 = up2(acc[tp][3]);
        int t = t0 + 2*tp;
        if (c0 < 64) {
            *(float4*)(&sqv[t][c0])   = make_float4(p0.x,p1.x,p2.x,p3.x);
            *(float4*)(&sqv[t+1][c0]) = make_float4(p0.y,p1.y,p2.y,p3.y);
        } else if (c0 < 128) {
            *(float4*)(&skv[t][c0-64])   = make_float4(p0.x,p1.x,p2.x,p3.x);
            *(float4*)(&skv[t+1][c0-64]) = make_float4(p0.y,p1.y,p2.y,p3.y);
        } else if (c0 < 192) {
            int cv = c0-128, hh = cv >> 4, off = cv & 15;
            int s = n0 + t - b*S_;
            *(float4*)(g_v + ((size_t)(b*NH_+hh)*S_ + s)*DH_ + off) =
                make_float4(p0.x,p1.x,p2.x,p3.x);
            *(float4*)(g_v + ((size_t)(b*NH_+hh)*S_ + s+1)*DH_ + off) =
                make_float4(p0.y,p1.y,p2.y,p3.y);
        }
    }
    __syncthreads();
    {
        int t = tid >> 3, h = (tid >> 1) & 3, half = tid & 1;
        int s = n0 + t - b*S_;
        float qh[16], kh[16];
        #pragma unroll
        for (int d = 0; d < 16; d++) { qh[d] = sqv[t][h*16+d]; kh[d] = skv[t][h*16+d]; }
        float dgq = 0.f, dgk = 0.f;
        #pragma unroll
        for (int d = 0; d < 16; d++) { dgq += qh[d]*qh[d]; dgk += kh[d]*kh[d]; }
        dgq *= 0.125f; dgk *= 0.125f;
        float dq[16];
        float mxq = -1e30f, mxk = -1e30f;
        size_t base = ((size_t)(b*NH_+h)*S_ + s)*M_ + half*16;
        #pragma unroll
        for (int m4 = 0; m4 < 16; m4 += 4) {
            float kk[4];
            #pragma unroll
            for (int mm = 0; mm < 4; mm++) {
                const float* pr = sproj + (half*16 + m4 + mm)*16;
                float aq = 0.f, ak = 0.f;
                #pragma unroll
                for (int d = 0; d < 16; d++) { aq += qh[d]*pr[d]; ak += kh[d]*pr[d]; }
                float dqv = 0.5f*aq, dkv = 0.5f*ak;
                dq[m4+mm] = dqv;
                mxq = fmaxf(mxq, dqv); mxk = fmaxf(mxk, dkv);
                kk[mm] = dkv - dgk;
            }
            *(float4*)(g_kp + base + m4) = make_float4(kk[0],kk[1],kk[2],kk[3]);
        }
        mxq = fmaxf(mxq, __shfl_xor_sync(~0u, mxq, 1));
        float mk = mxk;
        #pragma unroll
        for (int o = 16; o; o >>= 1) mk = fmaxf(mk, __shfl_xor_sync(~0u, mk, o));
        if ((tid & 31) == 0) atomicMax(&g_kmax_bits, enc_max(mk));
        // q features -> fp16 (16 halves = 2x uint4)
        __half2 qh2[8];
        #pragma unroll
        for (int m2 = 0; m2 < 8; m2++) {
            float a0 = RATIO_*(__expf(dq[m2*2]   - dgq - mxq) + 1e-4f);
            float a1 = RATIO_*(__expf(dq[m2*2+1] - dgq - mxq) + 1e-4f);
            qh2[m2] = __floats2half2_rn(a0, a1);
        }
        *(uint4*)(g_qp + base)     = *(uint4*)&qh2[0];
        *(uint4*)(g_qp + base + 8) = *(uint4*)&qh2[4];
    }
}

// per-chunk K / K^T V sums (exp in smem only). 2 chunks/block.
__global__ void __launch_bounds__(256) k_chunksum() {
    __shared__ float skp[2][64][33];
    __shared__ float sv [2][64][16];
    int tid = threadIdx.x, half = tid >> 7, lt = tid & 127;
    int ch = blockIdx.x*2 + half;
    float kmax = dec_max(g_kmax_bits);
    size_t kbase = (size_t)ch*CHUNK_*M_;
    size_t vbase = (size_t)ch*CHUNK_*DH_;
    for (int f = lt; f < 512; f += 128) {
        float4 a = *(const float4*)(g_kp + kbase + (f<<2));
        a.x = RATIO_*(__expf(a.x-kmax)+1e-4f); a.y = RATIO_*(__expf(a.y-kmax)+1e-4f);
        a.z = RATIO_*(__expf(a.z-kmax)+1e-4f); a.w = RATIO_*(__expf(a.w-kmax)+1e-4f);
        int s = f >> 3, m0 = (f & 7) << 2;
        skp[half][s][m0]=a.x; skp[half][s][m0+1]=a.y;
        skp[half][s][m0+2]=a.z; skp[half][s][m0+3]=a.w;
    }
    for (int f = lt; f < 256; f += 128)
        *(float4*)(&sv[half][f>>2][(f&3)<<2]) = *(const float4*)(g_v + vbase + (f<<2));
    __syncthreads();
    int m0 = (lt >> 3)*2, d0 = (lt & 7)*2;
    ull a0 = 0ull, a1 = 0ull;
    #pragma unroll 8
    for (int s = 0; s < 64; s++) {
        ull vp = *(const ull*)&sv[half][s][d0];
        a0 = ffma2(pk2(skp[half][s][m0],   skp[half][s][m0]),   vp, a0);
        a1 = ffma2(pk2(skp[half][s][m0+1], skp[half][s][m0+1]), vp, a1);
    }
    float2 r0 = up2(a0), r1 = up2(a1);
    size_t cb = (size_t)ch*CSZ_;
    g_chunk[cb + m0*16 + d0]   = r0.x; g_chunk[cb + m0*16 + d0+1]   = r0.y;
    g_chunk[cb + (m0+1)*16+d0] = r1.x; g_chunk[cb + (m0+1)*16+d0+1] = r1.y;
    if (lt < 32) {
        float s2 = 0.f;
        #pragma unroll 8
        for (int s = 0; s < 64; s++) s2 += skp[half][s][lt];
        g_chunk[cb + 512 + lt] = s2;
    }
}

// segment sums (float4)
__global__ void k_scanA() {
    int e4 = threadIdx.x*4;
    int bh = blockIdx.x / NSEG_, seg = blockIdx.x % NSEG_;
    int c0 = seg*SEG_;
    float4 s = make_float4(0,0,0,0);
    for (int ci = 0; ci < SEG_; ci++) {
        float4 v = *(const float4*)(g_chunk + ((size_t)(bh*NCHBH_ + c0 + ci))*CSZ_ + e4);
        s.x += v.x; s.y += v.y; s.z += v.z; s.w += v.w;
    }
    *(float4*)(g_seg + (size_t)blockIdx.x*CSZ_ + e4) = s;
}
// exclusive prefix within segment, offset by prior segment sums (float4)
__global__ void k_scanC() {
    int e4 = threadIdx.x*4;
    int bh = blockIdx.x / NSEG_, seg = blockIdx.x % NSEG_;
    float4 run = make_float4(0,0,0,0);
    for (int g = 0; g < seg; g++) {
        float4 v = *(const float4*)(g_seg + (size_t)(bh*NSEG_+g)*CSZ_ + e4);
        run.x += v.x; run.y += v.y; run.z += v.z; run.w += v.w;
    }
    int c0 = seg*SEG_;
    for (int ci = 0; ci < SEG_; ci++) {
        float* p = g_chunk + ((size_t)(bh*NCHBH_ + c0 + ci))*CSZ_ + e4;
        float4 v = *(const float4*)p;
        *(float4*)p = run;
        run.x += v.x; run.y += v.y; run.z += v.z; run.w += v.w;
    }
}

// intra-chunk causal attention (exp on load, FFMA2 tiles, fp16 q load)
__global__ void __launch_bounds__(256) k_intra() {
    __shared__ float sq [64][33];
    __shared__ float skt[32][66];
    __shared__ float sv [64][16];
    __shared__ float sA [64][68];
    __shared__ float sctx[32][16], sk0[32], rden[64];
    int tid = threadIdx.x, ch = blockIdx.x;
    float kmax = dec_max(g_kmax_bits);
    size_t fbase = (size_t)ch*CHUNK_*M_;
    size_t vbase = (size_t)ch*CHUNK_*DH_;
    size_t cb = (size_t)ch*CSZ_;
    // q: 64 tokens x 32 halves = 256 uint4 loads
    {
        int f = tid;   // 0..255
        int s = f >> 2, m0 = (f & 3)*8;
        uint4 raw = *(const uint4*)(g_qp + fbase + (size_t)s*M_ + m0);
        __half2* h2 = (__half2*)&raw;
        #pragma unroll
        for (int k2 = 0; k2 < 4; k2++) {
            float2 fv = __half22float2(h2[k2]);
            sq[s][m0 + k2*2]     = fv.x;
            sq[s][m0 + k2*2 + 1] = fv.y;
        }
    }
    for (int f = tid; f < 512; f += 256) {
        int s = f >> 3, m0 = (f & 7) << 2;
        float4 b = *(const float4*)(g_kp + fbase + (f<<2));
        skt[m0][s]   = RATIO_*(__expf(b.x-kmax)+1e-4f);
        skt[m0+1][s] = RATIO_*(__expf(b.y-kmax)+1e-4f);
        skt[m0+2][s] = RATIO_*(__expf(b.z-kmax)+1e-4f);
        skt[m0+3][s] = RATIO_*(__expf(b.w-kmax)+1e-4f);
    }
    *(float4*)(&sv[tid>>2][(tid&3)<<2]) = *(const float4*)(g_v + vbase + (tid<<2));
    if (tid < 128)
        *(float4*)(&sctx[tid>>2][(tid&3)<<2]) = *(const float4*)(g_chunk + cb + (tid<<2));
    if (tid < 8) *(float4*)(sk0 + tid*4) = *(const float4*)(g_chunk + cb + 512 + tid*4);
    __syncthreads();
    {
        int i0 = (tid >> 4)*4, j0 = (tid & 15)*4;
        if (j0 <= i0 + 3) {
            ull a[4][2];
            #pragma unroll
            for (int r = 0; r < 4; r++) { a[r][0]=0ull; a[r][1]=0ull; }
            #pragma unroll 4
            for (int m = 0; m < 32; m++) {
                ull kp01 = *(const ull*)&skt[m][j0];
                ull kp23 = *(const ull*)&skt[m][j0+2];
                #pragma unroll
                for (int r = 0; r < 4; r++) {
                    ull qb = pk2(sq[i0+r][m], sq[i0+r][m]);
                    a[r][0] = ffma2(qb, kp01, a[r][0]);
                    a[r][1] = ffma2(qb, kp23, a[r][1]);
                }
            }
            #pragma unroll
            for (int r = 0; r < 4; r++) {
                float2 p0 = up2(a[r][0]), p1 = up2(a[r][1]);
                *(float4*)(&sA[i0+r][j0]) = make_float4(p0.x,p0.y,p1.x,p1.y);
            }
        }
    }
    __syncthreads();
    if (tid < 64) {
        int i = tid;
        float den = 0.f;
        #pragma unroll 8
        for (int m = 0; m < 32; m++) den += sq[i][m]*sk0[m];
        for (int j = 0; j <= i; j++) den += sA[i][j];
        rden[i] = 1.f/den;
    }
    __syncthreads();
    {
        int i = tid >> 2, d0 = (tid & 3) << 2;
        ull acc0 = 0ull, acc1 = 0ull;
        #pragma unroll 8
        for (int m = 0; m < 32; m++) {
            ull qb = pk2(sq[i][m], sq[i][m]);
            acc0 = ffma2(qb, *(const ull*)&sctx[m][d0],   acc0);
            acc1 = ffma2(qb, *(const ull*)&sctx[m][d0+2], acc1);
        }
        for (int j = 0; j <= i; j++) {
            ull ab = pk2(sA[i][j], sA[i][j]);
            acc0 = ffma2(ab, *(const ull*)&sv[j][d0],   acc0);
            acc1 = ffma2(ab, *(const ull*)&sv[j][d0+2], acc1);
        }
        float2 p0 = up2(acc0), p1 = up2(acc1);
        float r = rden[i];
        *(float4*)(g_v + vbase + i*16 + d0) = make_float4(p0.x*r,p0.y*r,p1.x*r,p1.y*r);
    }
}

// fused: o-proj + residual + LN2 + FF (gelu, fp16 activations) + residual
__global__ void __launch_bounds__(256) k_post(
        const float* __restrict__ wo, const float* __restrict__ bo,
        const float* __restrict__ g2, const float* __restrict__ b2ln,
        const float* __restrict__ w1, const float* __restrict__ b1,
        const float* __restrict__ w2, const float* __restrict__ b2) {
    __shared__ float sbuf[32*68];      // phase1: sa[t][c]; phase2+: sht[d][t]
    __shared__ float st [32][68];
    __shared__ __half2 sg2[32][132];
    __shared__ float smu[32], sinv[32];
    #define SA_(t,c) sbuf[(t)*68+(c)]
    #define SHT_(d,t) sbuf[(d)*34+(t)]
    int tid = threadIdx.x;
    int n0 = blockIdx.x*32, b = n0 / S_;
    for (int f = tid; f < 512; f += 256) {
        int t = f >> 4, c4 = f & 15;
        int s = n0 + t - b*S_;
        int hh = c4 >> 2, off = (c4 & 3) << 2;
        *(float4*)(&SA_(t, c4*4)) =
            *(const float4*)(g_v + ((size_t)(b*NH_+hh)*S_ + s)*DH_ + off);
        int d4 = c4 << 2;
        *(float4*)(&st[t][d4]) = *(const float4*)(g_tokens + (size_t)(n0+t)*64 + d4);
    }
    __syncthreads();
    {
        int c0 = (tid & 15)*4, t0 = (tid >> 4)*2;
        ull a00=0ull,a01=0ull,a10=0ull,a11=0ull;
        #pragma unroll 4
        for (int i = 0; i < 64; i++) {
            float4 w = *(const float4*)(wo + i*64 + c0);
            ull wlo = pk2(w.x,w.y), whi = pk2(w.z,w.w);
            ull h0 = pk2(SA_(t0,i), SA_(t0,i));
            ull h1 = pk2(SA_(t0+1,i), SA_(t0+1,i));
            a00 = ffma2(h0, wlo, a00); a01 = ffma2(h0, whi, a01);
            a10 = ffma2(h1, wlo, a10); a11 = ffma2(h1, whi, a11);
        }
        float4 bv = *(const float4*)(bo + c0);
        float2 p0 = up2(a00), p1 = up2(a01), p2 = up2(a10), p3 = up2(a11);
        float4 r = *(float4*)(&st[t0][c0]);
        r.x += p0.x+bv.x; r.y += p0.y+bv.y; r.z += p1.x+bv.z; r.w += p1.y+bv.w;
        *(float4*)(&st[t0][c0]) = r;
        float4 r2 = *(float4*)(&st[t0+1][c0]);
        r2.x += p2.x+bv.x; r2.y += p2.y+bv.y; r2.z += p3.x+bv.z; r2.w += p3.y+bv.w;
        *(float4*)(&st[t0+1][c0]) = r2;
    }
    __syncthreads();
    if (tid < 32) {
        float s = 0.f, ss = 0.f;
        #pragma unroll 8
        for (int d = 0; d < 64; d++) { float v = st[tid][d]; s += v; ss += v*v; }
        float mu = s*(1.f/64.f);
        smu[tid] = mu;
        sinv[tid] = rsqrtf(ss*(1.f/64.f) - mu*mu + 1e-5f);
    }
    __syncthreads();
    for (int e = tid; e < 2048; e += 256) {
        int t = e >> 6, d = e & 63;
        SHT_(d,t) = (st[t][d] - smu[t])*sinv[t]*g2[d] + b2ln[d];
    }
    __syncthreads();
    {
        int c0 = (tid & 63)*4, t0 = (tid >> 6)*8;
        ull acc[4][4];
        #pragma unroll
        for (int tp = 0; tp < 4; tp++)
            #pragma unroll
            for (int c = 0; c < 4; c++) acc[tp][c] = 0ull;
        #pragma unroll 4
        for (int d = 0; d < 64; d++) {
            float4 w = *(const float4*)(w1 + d*256 + c0);
            ull wb0 = pk2(w.x,w.x), wb1 = pk2(w.y,w.y), wb2 = pk2(w.z,w.z), wb3 = pk2(w.w,w.w);
            #pragma unroll
            for (int tp = 0; tp < 4; tp++) {
                ull hp = *(const ull*)&SHT_(d, t0 + 2*tp);
                acc[tp][0] = ffma2(hp, wb0, acc[tp][0]);
                acc[tp][1] = ffma2(hp, wb1, acc[tp][1]);
                acc[tp][2] = ffma2(hp, wb2, acc[tp][2]);
                acc[tp][3] = ffma2(hp, wb3, acc[tp][3]);
            }
        }
        float4 bv = *(const float4*)(b1 + c0);
        #pragma unroll
        for (int tp = 0; tp < 4; tp++) {
            float2 p0 = up2(acc[tp][0]), p1 = up2(acc[tp][1]);
            float2 p2 = up2(acc[tp][2]), p3 = up2(acc[tp][3]);
            int t = t0 + 2*tp;
            float u; float4 o;
            u = p0.x+bv.x; o.x = 0.5f*u*(1.f+erff(u*0.70710678f));
            u = p1.x+bv.y; o.y = 0.5f*u*(1.f+erff(u*0.70710678f));
            u = p2.x+bv.z; o.z = 0.5f*u*(1.f+erff(u*0.70710678f));
            u = p3.x+bv.w; o.w = 0.5f*u*(1.f+erff(u*0.70710678f));
            sg2[t][(c0>>1)]   = __floats2half2_rn(o.x, o.y);
            sg2[t][(c0>>1)+1] = __floats2half2_rn(o.z, o.w);
            u = p0.y+bv.x; o.x = 0.5f*u*(1.f+erff(u*0.70710678f));
            u = p1.y+bv.y; o.y = 0.5f*u*(1.f+erff(u*0.70710678f));
            u = p2.y+bv.z; o.z = 0.5f*u*(1.f+erff(u*0.70710678f));
            u = p3.y+bv.w; o.w = 0.5f*u*(1.f+erff(u*0.70710678f));
            sg2[t+1][(c0>>1)]   = __floats2half2_rn(o.x, o.y);
            sg2[t+1][(c0>>1)+1] = __floats2half2_rn(o.z, o.w);
        }
    }
    __syncthreads();
    {
        int c0 = (tid & 15)*4, t0 = (tid >> 4)*2;
        ull a00=0ull,a01=0ull,a10=0ull,a11=0ull;
        #pragma unroll 4
        for (int fp = 0; fp < 128; fp++) {
            float2 h0f = __half22float2(sg2[t0][fp]);
            float2 h1f = __half22float2(sg2[t0+1][fp]);
            int f = fp*2;
            float4 wA = *(const float4*)(w2 + f*64 + c0);
            float4 wB = *(const float4*)(w2 + (f+1)*64 + c0);
            ull wloA = pk2(wA.x,wA.y), whiA = pk2(wA.z,wA.w);
            ull wloB = pk2(wB.x,wB.y), whiB = pk2(wB.z,wB.w);
            ull h00 = pk2(h0f.x,h0f.x), h01 = pk2(h0f.y,h0f.y);
            ull h10 = pk2(h1f.x,h1f.x), h11 = pk2(h1f.y,h1f.y);
            a00 = ffma2(h00, wloA, a00); a01 = ffma2(h00, whiA, a01);
            a10 = ffma2(h10, wloA, a10); a11 = ffma2(h10, whiA, a11);
            a00 = ffma2(h01, wloB, a00); a01 = ffma2(h01, whiB, a01);
            a10 = ffma2(h11, wloB, a10); a11 = ffma2(h11, whiB, a11);
        }
        float4 bv = *(const float4*)(b2 + c0);
        float2 p0 = up2(a00), p1 = up2(a01), p2 = up2(a10), p3 = up2(a11);
        float4 r = *(float4*)(&st[t0][c0]);
        r.x += p0.x+bv.x; r.y += p0.y+bv.y; r.z += p1.x+bv.z; r.w += p1.y+bv.w;
        *(float4*)(g_tokens + (size_t)(n0+t0)*64 + c0) = r;
        float4 r2 = *(float4*)(&st[t0+1][c0]);
        r2.x += p2.x+bv.x; r2.y += p2.y+bv.y; r2.z += p3.x+bv.z; r2.w += p3.y+bv.w;
        *(float4*)(g_tokens + (size_t)(n0+t0+1)*64 + c0) = r2;
    }
    #undef SA_
    #undef SHT_
}

// fused readout: mean-over-T + 5x5 conv (pad 2) + spatial sum via clipped tap sums
__global__ void k_read(const float* __restrict__ x, const float* __restrict__ tw) {
    int idx = blockIdx.x*256 + threadIdx.x;
    int hw = idx % HW_;
    int t2 = idx / HW_;
    int c = t2 % (D_+1), b = t2 / (D_+1);
    float v;
    if (c < D_) {
        float acc = 0.f;
        #pragma unroll
        for (int t = 0; t < T_; t++)
            acc += g_tokens[(size_t)b*S_*64 + (size_t)c*THW_ + t*HW_ + hw];
        v = acc*(1.f/T_);
    } else {
        v = x[((size_t)b*3 + 2)*THW_ + hw];
    }
    int y = hw / WW_, xx = hw % WW_;
    int kylo = max(0, y-45), kyhi = min(4, y+2);
    int kxlo = max(0, xx-45), kxhi = min(4, xx+2);
    float w = 0.f;
    for (int ky = kylo; ky <= kyhi; ky++)
        for (int kx = kxlo; kx <= kxhi; kx++)
            w += tw[c*25 + ky*5 + kx];
    float contrib = v*w;
    __shared__ float red[256];
    red[threadIdx.x] = contrib; __syncthreads();
    #pragma unroll
    for (int o = 128; o; o >>= 1) {
        if (threadIdx.x < o) red[threadIdx.x] += red[threadIdx.x + o];
        __syncthreads();
    }
    if (threadIdx.x == 0) atomicAdd(&g_accum[b], red[0]);
}

__global__ void k_final(const float* __restrict__ tb, const float* __restrict__ rw,
                        const float* __restrict__ rb, float* __restrict__ out) {
    int b = threadIdx.x;
    if (b < B_) out[b] = (g_accum[b]*(1.f/HW_) + tb[0])*rw[0] + rb[0];
}

extern "C" void kernel_launch(void* const* d_in, const int* in_sizes, int n_in,
                              void* d_out, int out_size) {
    const float* x    = (const float*)d_in[0];
    const float* prw  = (const float*)d_in[1];
    const float* prb  = (const float*)d_in[2];
    const float* ln1g = (const float*)d_in[3];
    const float* ln1b = (const float*)d_in[4];
    const float* wq   = (const float*)d_in[5];
    const float* wk   = (const float*)d_in[6];
    const float* wv   = (const float*)d_in[7];
    const float* wo   = (const float*)d_in[8];
    const float* bo   = (const float*)d_in[9];
    const float* proj = (const float*)d_in[10];
    const float* ln2g = (const float*)d_in[11];
    const float* ln2b = (const float*)d_in[12];
    const float* w1   = (const float*)d_in[13];
    const float* b1   = (const float*)d_in[14];
    const float* w2   = (const float*)d_in[15];
    const float* b2   = (const float*)d_in[16];
    const float* tw   = (const float*)d_in[17];
    const float* tb   = (const float*)d_in[18];
    const float* rw   = (const float*)d_in[19];
    const float* rb   = (const float*)d_in[20];
    float* out = (float*)d_out;

    k_init<<<1, 32>>>();
    k_qkv<<<N_/32, 256>>>(x, prw, prb, ln1g, ln1b, wq, wk, wv, proj);
    k_chunksum<<<NCH_/2, 256>>>();
    k_scanA<<<B_*NH_*NSEG_, CSZ_/4>>>();
    k_scanC<<<B_*NH_*NSEG_, CSZ_/4>>>();
    k_intra<<<NCH_, 256>>>();
    k_post<<<N_/32, 256>>>(wo, bo, ln2g, ln2b, w1, b1, w2, b2);
    k_read<<<(B_*(D_+1)*HW_)/256, 256>>>(x, tw);
    k_final<<<1, 32>>>(tb, rw, rb, out);
}

// round 17
// speedup vs baseline: 1.0193x; 1.0175x over previous
#include <cuda_runtime.h>
#include <cuda_fp16.h>
#include <math.h>

#define B_ 2
#define T_ 8
#define HH_ 48
#define WW_ 48
#define D_ 64
#define DH_ 16
#define NH_ 4
#define M_ 32
#define FFD_ 256
#define HW_ (HH_*WW_)
#define THW_ (T_*HW_)
#define S_ THW_
#define N_ (B_*S_)
#define CHUNK_ 64
#define NCHBH_ (S_/CHUNK_)     // 288
#define NCH_ (B_*NH_*NCHBH_)   // 2304
#define CSZ_ (M_*DH_+M_)       // 544
#define SEG_ 16
#define NSEG_ (NCHBH_/SEG_)    // 18
#define RATIO_ 0.17677669529663687f

typedef unsigned long long ull;
__device__ __forceinline__ ull ffma2(ull a, ull b, ull c) {
    ull d; asm("fma.rn.f32x2 %0, %1, %2, %3;" : "=l"(d) : "l"(a), "l"(b), "l"(c));
    return d;
}
__device__ __forceinline__ ull pk2(float lo, float hi) {
    ull r; asm("mov.b64 %0, {%1, %2};" : "=l"(r) : "f"(lo), "f"(hi)); return r;
}
__device__ __forceinline__ float2 up2(ull v) {
    float2 r; asm("mov.b64 {%0, %1}, %2;" : "=f"(r.x), "=f"(r.y) : "l"(v)); return r;
}
// pack 4 floats -> 4 halves (uint2)
__device__ __forceinline__ uint2 h4(float a, float b, float c, float d) {
    __half2 lo = __floats2half2_rn(a, b), hi = __floats2half2_rn(c, d);
    uint2 r; r.x = *(unsigned*)&lo; r.y = *(unsigned*)&hi; return r;
}
__device__ __forceinline__ float4 uh4(uint2 v) {
    float2 lo = __half22float2(*(__half2*)&v.x);
    float2 hi = __half22float2(*(__half2*)&v.y);
    return make_float4(lo.x, lo.y, hi.x, hi.y);
}

__device__ float g_tokens[B_*S_*D_];
__device__ __half g_qp[B_*NH_*S_*M_];   // q features fp16
__device__ float g_kp[B_*NH_*S_*M_];
__device__ __half g_v [B_*NH_*S_*DH_];  // v / attn-out fp16
__device__ float g_chunk[NCH_*CSZ_];
__device__ float g_seg[B_*NH_*NSEG_*CSZ_];
__device__ float g_accum[B_];
__device__ unsigned g_kmax_bits;

__device__ __forceinline__ unsigned enc_max(float f) {
    unsigned b = __float_as_uint(f);
    return (b & 0x80000000u) ? ~b : (b | 0x80000000u);
}
__device__ __forceinline__ float dec_max(unsigned u) {
    return __uint_as_float((u & 0x80000000u) ? (u & 0x7fffffffu) : ~u);
}

__global__ void k_init() {
    if (threadIdx.x == 0) g_kmax_bits = 0u;
    if (threadIdx.x < B_) g_accum[threadIdx.x] = 0.f;
}

// preproc(conv1x1+softplus, writes g_tokens) + LN1 + QKV (FFMA2) + FAVOR+ features
__global__ void __launch_bounds__(256) k_qkv(
        const float* __restrict__ x, const float* __restrict__ pw,
        const float* __restrict__ pb,
        const float* __restrict__ ln_g, const float* __restrict__ ln_b,
        const float* __restrict__ wq, const float* __restrict__ wk,
        const float* __restrict__ wv, const float* __restrict__ proj) {
    __shared__ float sht[64][34];
    __shared__ float sqv[32][68], skv[32][68];
    __shared__ float smu[32], sinv[32], sproj[512];
    int tid = threadIdx.x;
    int n0 = blockIdx.x*32, b = n0 / S_;
    if (tid < 128) *(float4*)(sproj + tid*4) = *(const float4*)(proj + tid*4);
    {
        int f0 = (n0 - b*S_)*64;
        int dd = f0 / THW_, p0 = f0 - dd*THW_;
        const float* xb = x + (size_t)b*3*THW_ + p0;
        float w0 = pw[dd*3], w1 = pw[dd*3+1], w2 = pw[dd*3+2], bb = pb[dd];
        for (int f = tid; f < 512; f += 256) {
            int j4 = f*4;
            float4 c0 = *(const float4*)(xb + j4);
            float4 c1 = *(const float4*)(xb + THW_ + j4);
            float4 c2 = *(const float4*)(xb + 2*THW_ + j4);
            float4 o; float v;
            v = bb + w0*c0.x + w1*c1.x + w2*c2.x; o.x = (v>20.f)?v:__logf(1.f+__expf(v));
            v = bb + w0*c0.y + w1*c1.y + w2*c2.y; o.y = (v>20.f)?v:__logf(1.f+__expf(v));
            v = bb + w0*c0.z + w1*c1.z + w2*c2.z; o.z = (v>20.f)?v:__logf(1.f+__expf(v));
            v = bb + w0*c0.w + w1*c1.w + w2*c2.w; o.w = (v>20.f)?v:__logf(1.f+__expf(v));
            *(float4*)(g_tokens + (size_t)n0*64 + j4) = o;
            int t = j4 >> 6, d = j4 & 63;
            sht[d][t]=o.x; sht[d+1][t]=o.y; sht[d+2][t]=o.z; sht[d+3][t]=o.w;
        }
    }
    __syncthreads();
    if (tid < 32) {
        float s = 0.f, ss = 0.f;
        #pragma unroll 8
        for (int d = 0; d < 64; d++) { float v = sht[d][tid]; s += v; ss += v*v; }
        float mu = s*(1.f/64.f);
        smu[tid] = mu;
        sinv[tid] = rsqrtf(ss*(1.f/64.f) - mu*mu + 1e-5f);
    }
    __syncthreads();
    for (int e = tid; e < 2048; e += 256) {
        int d = e >> 5, t = e & 31;
        sht[d][t] = (sht[d][t] - smu[t])*sinv[t]*ln_g[d] + ln_b[d];
    }
    __syncthreads();
    int cg = tid & 63, tg = tid >> 6;
    int c0 = cg*4, t0 = tg*8;
    const float* wptr = (c0 < 64) ? wq + c0 : (c0 < 128) ? wk + (c0-64)
                       : (c0 < 192) ? wv + (c0-128) : wq;
    ull acc[4][4];
    #pragma unroll
    for (int tp = 0; tp < 4; tp++)
        #pragma unroll
        for (int c = 0; c < 4; c++) acc[tp][c] = 0ull;
    #pragma unroll 4
    for (int d = 0; d < 64; d++) {
        float4 w = *(const float4*)(wptr + d*64);
        ull wb0 = pk2(w.x,w.x), wb1 = pk2(w.y,w.y), wb2 = pk2(w.z,w.z), wb3 = pk2(w.w,w.w);
        #pragma unroll
        for (int tp = 0; tp < 4; tp++) {
            ull hp = *(const ull*)&sht[d][t0 + 2*tp];
            acc[tp][0] = ffma2(hp, wb0, acc[tp][0]);
            acc[tp][1] = ffma2(hp, wb1, acc[tp][1]);
            acc[tp][2] = ffma2(hp, wb2, acc[tp][2]);
            acc[tp][3] = ffma2(hp, wb3, acc[tp][3]);
        }
    }
    #pragma unroll
    for (int tp = 0; tp < 4; tp++) {
        float2 p0 = up2(acc[tp][0]), p1 = up2(acc[tp][1]);
        float2 p2 = up2(acc[tp][2]), p3 = up2(acc[tp][3]);
        int t = t0 + 2*tp;
        if (c0 < 64) {
            *(float4*)(&sqv[t][c0])   = make_float4(p0.x,p1.x,p2.x,p3.x);
            *(float4*)(&sqv[t+1][c0]) = make_float4(p0.y,p1.y,p2.y,p3.y);
        } else if (c0 < 128) {
            *(float4*)(&skv[t][c0-64])   = make_float4(p0.x,p1.x,p2.x,p3.x);
            *(float4*)(&skv[t+1][c0-64]) = make_float4(p0.y,p1.y,p2.y,p3.y);
        } else if (c0 < 192) {
            int cv = c0-128, hh = cv >> 4, off = cv & 15;
            int s = n0 + t - b*S_;
            *(uint2*)(g_v + ((size_t)(b*NH_+hh)*S_ + s)*DH_ + off) =
                h4(p0.x,p1.x,p2.x,p3.x);
            *(uint2*)(g_v + ((size_t)(b*NH_+hh)*S_ + s+1)*DH_ + off) =
                h4(p0.y,p1.y,p2.y,p3.y);
        }
    }
    __syncthreads();
    {
        int t = tid >> 3, h = (tid >> 1) & 3, half = tid & 1;
        int s = n0 + t - b*S_;
        float qh[16], kh[16];
        #pragma unroll
        for (int d = 0; d < 16; d++) { qh[d] = sqv[t][h*16+d]; kh[d] = skv[t][h*16+d]; }
        float dgq = 0.f, dgk = 0.f;
        #pragma unroll
        for (int d = 0; d < 16; d++) { dgq += qh[d]*qh[d]; dgk += kh[d]*kh[d]; }
        dgq *= 0.125f; dgk *= 0.125f;
        float dq[16];
        float mxq = -1e30f, mxk = -1e30f;
        size_t base = ((size_t)(b*NH_+h)*S_ + s)*M_ + half*16;
        #pragma unroll
        for (int m4 = 0; m4 < 16; m4 += 4) {
            float kk[4];
            #pragma unroll
            for (int mm = 0; mm < 4; mm++) {
                const float* pr = sproj + (half*16 + m4 + mm)*16;
                float aq = 0.f, ak = 0.f;
                #pragma unroll
                for (int d = 0; d < 16; d++) { aq += qh[d]*pr[d]; ak += kh[d]*pr[d]; }
                float dqv = 0.5f*aq, dkv = 0.5f*ak;
                dq[m4+mm] = dqv;
                mxq = fmaxf(mxq, dqv); mxk = fmaxf(mxk, dkv);
                kk[mm] = dkv - dgk;
            }
            *(float4*)(g_kp + base + m4) = make_float4(kk[0],kk[1],kk[2],kk[3]);
        }
        mxq = fmaxf(mxq, __shfl_xor_sync(~0u, mxq, 1));
        float mk = mxk;
        #pragma unroll
        for (int o = 16; o; o >>= 1) mk = fmaxf(mk, __shfl_xor_sync(~0u, mk, o));
        if ((tid & 31) == 0) atomicMax(&g_kmax_bits, enc_max(mk));
        __half2 qh2[8];
        #pragma unroll
        for (int m2 = 0; m2 < 8; m2++) {
            float a0 = RATIO_*(__expf(dq[m2*2]   - dgq - mxq) + 1e-4f);
            float a1 = RATIO_*(__expf(dq[m2*2+1] - dgq - mxq) + 1e-4f);
            qh2[m2] = __floats2half2_rn(a0, a1);
        }
        *(uint4*)(g_qp + base)     = *(uint4*)&qh2[0];
        *(uint4*)(g_qp + base + 8) = *(uint4*)&qh2[4];
    }
}

// per-chunk K / K^T V sums (exp in smem only). 2 chunks/block.
__global__ void __launch_bounds__(256) k_chunksum() {
    __shared__ float skp[2][64][33];
    __shared__ float sv [2][64][16];
    int tid = threadIdx.x, half = tid >> 7, lt = tid & 127;
    int ch = blockIdx.x*2 + half;
    float kmax = dec_max(g_kmax_bits);
    size_t kbase = (size_t)ch*CHUNK_*M_;
    size_t vbase = (size_t)ch*CHUNK_*DH_;
    for (int f = lt; f < 512; f += 128) {
        float4 a = *(const float4*)(g_kp + kbase + (f<<2));
        a.x = RATIO_*(__expf(a.x-kmax)+1e-4f); a.y = RATIO_*(__expf(a.y-kmax)+1e-4f);
        a.z = RATIO_*(__expf(a.z-kmax)+1e-4f); a.w = RATIO_*(__expf(a.w-kmax)+1e-4f);
        int s = f >> 3, m0 = (f & 7) << 2;
        skp[half][s][m0]=a.x; skp[half][s][m0+1]=a.y;
        skp[half][s][m0+2]=a.z; skp[half][s][m0+3]=a.w;
    }
    for (int f = lt; f < 256; f += 128) {
        float4 v = uh4(*(const uint2*)(g_v + vbase + (f<<2)));
        *(float4*)(&sv[half][f>>2][(f&3)<<2]) = v;
    }
    __syncthreads();
    int m0 = (lt >> 3)*2, d0 = (lt & 7)*2;
    ull a0 = 0ull, a1 = 0ull;
    #pragma unroll 8
    for (int s = 0; s < 64; s++) {
        ull vp = *(const ull*)&sv[half][s][d0];
        a0 = ffma2(pk2(skp[half][s][m0],   skp[half][s][m0]),   vp, a0);
        a1 = ffma2(pk2(skp[half][s][m0+1], skp[half][s][m0+1]), vp, a1);
    }
    float2 r0 = up2(a0), r1 = up2(a1);
    size_t cb = (size_t)ch*CSZ_;
    g_chunk[cb + m0*16 + d0]   = r0.x; g_chunk[cb + m0*16 + d0+1]   = r0.y;
    g_chunk[cb + (m0+1)*16+d0] = r1.x; g_chunk[cb + (m0+1)*16+d0+1] = r1.y;
    if (lt < 32) {
        float s2 = 0.f;
        #pragma unroll 8
        for (int s = 0; s < 64; s++) s2 += skp[half][s][lt];
        g_chunk[cb + 512 + lt] = s2;
    }
}

// segment sums (float4)
__global__ void k_scanA() {
    int e4 = threadIdx.x*4;
    int bh = blockIdx.x / NSEG_, seg = blockIdx.x % NSEG_;
    int c0 = seg*SEG_;
    float4 s = make_float4(0,0,0,0);
    for (int ci = 0; ci < SEG_; ci++) {
        float4 v = *(const float4*)(g_chunk + ((size_t)(bh*NCHBH_ + c0 + ci))*CSZ_ + e4);
        s.x += v.x; s.y += v.y; s.z += v.z; s.w += v.w;
    }
    *(float4*)(g_seg + (size_t)blockIdx.x*CSZ_ + e4) = s;
}
// exclusive prefix within segment, offset by prior segment sums (float4)
__global__ void k_scanC() {
    int e4 = threadIdx.x*4;
    int bh = blockIdx.x / NSEG_, seg = blockIdx.x % NSEG_;
    float4 run = make_float4(0,0,0,0);
    for (int g = 0; g < seg; g++) {
        float4 v = *(const float4*)(g_seg + (size_t)(bh*NSEG_+g)*CSZ_ + e4);
        run.x += v.x; run.y += v.y; run.z += v.z; run.w += v.w;
    }
    int c0 = seg*SEG_;
    for (int ci = 0; ci < SEG_; ci++) {
        float* p = g_chunk + ((size_t)(bh*NCHBH_ + c0 + ci))*CSZ_ + e4;
        float4 v = *(const float4*)p;
        *(float4*)p = run;
        run.x += v.x; run.y += v.y; run.z += v.z; run.w += v.w;
    }
}

// intra-chunk causal attention (exp on load, FFMA2 tiles, fp16 q/v)
__global__ void __launch_bounds__(256) k_intra() {
    __shared__ float sq [64][33];
    __shared__ float skt[32][66];
    __shared__ float sv [64][16];
    __shared__ float sA [64][68];
    __shared__ float sctx[32][16], sk0[32], rden[64];
    int tid = threadIdx.x, ch = blockIdx.x;
    float kmax = dec_max(g_kmax_bits);
    size_t fbase = (size_t)ch*CHUNK_*M_;
    size_t vbase = (size_t)ch*CHUNK_*DH_;
    size_t cb = (size_t)ch*CSZ_;
    {
        int f = tid;
        int s = f >> 2, m0 = (f & 3)*8;
        uint4 raw = *(const uint4*)(g_qp + fbase + (size_t)s*M_ + m0);
        __half2* h2 = (__half2*)&raw;
        #pragma unroll
        for (int k2 = 0; k2 < 4; k2++) {
            float2 fv = __half22float2(h2[k2]);
            sq[s][m0 + k2*2]     = fv.x;
            sq[s][m0 + k2*2 + 1] = fv.y;
        }
    }
    for (int f = tid; f < 512; f += 256) {
        int s = f >> 3, m0 = (f & 7) << 2;
        float4 b = *(const float4*)(g_kp + fbase + (f<<2));
        skt[m0][s]   = RATIO_*(__expf(b.x-kmax)+1e-4f);
        skt[m0+1][s] = RATIO_*(__expf(b.y-kmax)+1e-4f);
        skt[m0+2][s] = RATIO_*(__expf(b.z-kmax)+1e-4f);
        skt[m0+3][s] = RATIO_*(__expf(b.w-kmax)+1e-4f);
    }
    {
        float4 v = uh4(*(const uint2*)(g_v + vbase + (tid<<2)));
        *(float4*)(&sv[tid>>2][(tid&3)<<2]) = v;
    }
    if (tid < 128)
        *(float4*)(&sctx[tid>>2][(tid&3)<<2]) = *(const float4*)(g_chunk + cb + (tid<<2));
    if (tid < 8) *(float4*)(sk0 + tid*4) = *(const float4*)(g_chunk + cb + 512 + tid*4);
    __syncthreads();
    {
        int i0 = (tid >> 4)*4, j0 = (tid & 15)*4;
        if (j0 <= i0 + 3) {
            ull a[4][2];
            #pragma unroll
            for (int r = 0; r < 4; r++) { a[r][0]=0ull; a[r][1]=0ull; }
            #pragma unroll 4
            for (int m = 0; m < 32; m++) {
                ull kp01 = *(const ull*)&skt[m][j0];
                ull kp23 = *(const ull*)&skt[m][j0+2];
                #pragma unroll
                for (int r = 0; r < 4; r++) {
                    ull qb = pk2(sq[i0+r][m], sq[i0+r][m]);
                    a[r][0] = ffma2(qb, kp01, a[r][0]);
                    a[r][1] = ffma2(qb, kp23, a[r][1]);
                }
            }
            #pragma unroll
            for (int r = 0; r < 4; r++) {
                float2 p0 = up2(a[r][0]), p1 = up2(a[r][1]);
                *(float4*)(&sA[i0+r][j0]) = make_float4(p0.x,p0.y,p1.x,p1.y);
            }
        }
    }
    __syncthreads();
    if (tid < 64) {
        int i = tid;
        float den = 0.f;
        #pragma unroll 8
        for (int m = 0; m < 32; m++) den += sq[i][m]*sk0[m];
        for (int j = 0; j <= i; j++) den += sA[i][j];
        rden[i] = 1.f/den;
    }
    __syncthreads();
    {
        int i = tid >> 2, d0 = (tid & 3) << 2;
        ull acc0 = 0ull, acc1 = 0ull;
        #pragma unroll 8
        for (int m = 0; m < 32; m++) {
            ull qb = pk2(sq[i][m], sq[i][m]);
            acc0 = ffma2(qb, *(const ull*)&sctx[m][d0],   acc0);
            acc1 = ffma2(qb, *(const ull*)&sctx[m][d0+2], acc1);
        }
        for (int j = 0; j <= i; j++) {
            ull ab = pk2(sA[i][j], sA[i][j]);
            acc0 = ffma2(ab, *(const ull*)&sv[j][d0],   acc0);
            acc1 = ffma2(ab, *(const ull*)&sv[j][d0+2], acc1);
        }
        float2 p0 = up2(acc0), p1 = up2(acc1);
        float r = rden[i];
        *(uint2*)(g_v + vbase + i*16 + d0) = h4(p0.x*r, p0.y*r, p1.x*r, p1.y*r);
    }
}

// fused: o-proj + residual + LN2 + FF (gelu, fp16 activations) + residual
__global__ void __launch_bounds__(256) k_post(
        const float* __restrict__ wo, const float* __restrict__ bo,
        const float* __restrict__ g2, const float* __restrict__ b2ln,
        const float* __restrict__ w1, const float* __restrict__ b1,
        const float* __restrict__ w2, const float* __restrict__ b2) {
    __shared__ float sbuf[32*68];
    __shared__ float st [32][68];
    __shared__ __half2 sg2[32][132];
    __shared__ float smu[32], sinv[32];
    #define SA_(t,c) sbuf[(t)*68+(c)]
    #define SHT_(d,t) sbuf[(d)*34+(t)]
    int tid = threadIdx.x;
    int n0 = blockIdx.x*32, b = n0 / S_;
    for (int f = tid; f < 512; f += 256) {
        int t = f >> 4, c4 = f & 15;
        int s = n0 + t - b*S_;
        int hh = c4 >> 2, off = (c4 & 3) << 2;
        float4 v = uh4(*(const uint2*)(g_v + ((size_t)(b*NH_+hh)*S_ + s)*DH_ + off));
        *(float4*)(&SA_(t, c4*4)) = v;
        int d4 = c4 << 2;
        *(float4*)(&st[t][d4]) = *(const float4*)(g_tokens + (size_t)(n0+t)*64 + d4);
    }
    __syncthreads();
    {
        int c0 = (tid & 15)*4, t0 = (tid >> 4)*2;
        ull a00=0ull,a01=0ull,a10=0ull,a11=0ull;
        #pragma unroll 4
        for (int i = 0; i < 64; i++) {
            float4 w = *(const float4*)(wo + i*64 + c0);
            ull wlo = pk2(w.x,w.y), whi = pk2(w.z,w.w);
            ull h0 = pk2(SA_(t0,i), SA_(t0,i));
            ull h1 = pk2(SA_(t0+1,i), SA_(t0+1,i));
            a00 = ffma2(h0, wlo, a00); a01 = ffma2(h0, whi, a01);
            a10 = ffma2(h1, wlo, a10); a11 = ffma2(h1, whi, a11);
        }
        float4 bv = *(const float4*)(bo + c0);
        float2 p0 = up2(a00), p1 = up2(a01), p2 = up2(a10), p3 = up2(a11);
        float4 r = *(float4*)(&st[t0][c0]);
        r.x += p0.x+bv.x; r.y += p0.y+bv.y; r.z += p1.x+bv.z; r.w += p1.y+bv.w;
        *(float4*)(&st[t0][c0]) = r;
        float4 r2 = *(float4*)(&st[t0+1][c0]);
        r2.x += p2.x+bv.x; r2.y += p2.y+bv.y; r2.z += p3.x+bv.z; r2.w += p3.y+bv.w;
        *(float4*)(&st[t0+1][c0]) = r2;
    }
    __syncthreads();
    if (tid < 32) {
        float s = 0.f, ss = 0.f;
        #pragma unroll 8
        for (int d = 0; d < 64; d++) { float v = st[tid][d]; s += v; ss += v*v; }
        float mu = s*(1.f/64.f);
        smu[tid] = mu;
        sinv[tid] = rsqrtf(ss*(1.f/64.f) - mu*mu + 1e-5f);
    }
    __syncthreads();
    for (int e = tid; e < 2048; e += 256) {
        int t = e >> 6, d = e & 63;
        SHT_(d,t) = (st[t][d] - smu[t])*sinv[t]*g2[d] + b2ln[d];
    }
    __syncthreads();
    {
        int c0 = (tid & 63)*4, t0 = (tid >> 6)*8;
        ull acc[4][4];
        #pragma unroll
        for (int tp = 0; tp < 4; tp++)
            #pragma unroll
            for (int c = 0; c < 4; c++) acc[tp][c] = 0ull;
        #pragma unroll 4
        for (int d = 0; d < 64; d++) {
            float4 w = *(const float4*)(w1 + d*256 + c0);
            ull wb0 = pk2(w.x,w.x), wb1 = pk2(w.y,w.y), wb2 = pk2(w.z,w.z), wb3 = pk2(w.w,w.w);
            #pragma unroll
            for (int tp = 0; tp < 4; tp++) {
                ull hp = *(const ull*)&SHT_(d, t0 + 2*tp);
                acc[tp][0] = ffma2(hp, wb0, acc[tp][0]);
                acc[tp][1] = ffma2(hp, wb1, acc[tp][1]);
                acc[tp][2] = ffma2(hp, wb2, acc[tp][2]);
                acc[tp][3] = ffma2(hp, wb3, acc[tp][3]);
            }
        }
        float4 bv = *(const float4*)(b1 + c0);
        #pragma unroll
        for (int tp = 0; tp < 4; tp++) {
            float2 p0 = up2(acc[tp][0]), p1 = up2(acc[tp][1]);
            float2 p2 = up2(acc[tp][2]), p3 = up2(acc[tp][3]);
            int t = t0 + 2*tp;
            float u; float4 o;
            u = p0.x+bv.x; o.x = 0.5f*u*(1.f+erff(u*0.70710678f));
            u = p1.x+bv.y; o.y = 0.5f*u*(1.f+erff(u*0.70710678f));
            u = p2.x+bv.z; o.z = 0.5f*u*(1.f+erff(u*0.70710678f));
            u = p3.x+bv.w; o.w = 0.5f*u*(1.f+erff(u*0.70710678f));
            sg2[t][(c0>>1)]   = __floats2half2_rn(o.x, o.y);
            sg2[t][(c0>>1)+1] = __floats2half2_rn(o.z, o.w);
            u = p0.y+bv.x; o.x = 0.5f*u*(1.f+erff(u*0.70710678f));
            u = p1.y+bv.y; o.y = 0.5f*u*(1.f+erff(u*0.70710678f));
            u = p2.y+bv.z; o.z = 0.5f*u*(1.f+erff(u*0.70710678f));
            u = p3.y+bv.w; o.w = 0.5f*u*(1.f+erff(u*0.70710678f));
            sg2[t+1][(c0>>1)]   = __floats2half2_rn(o.x, o.y);
            sg2[t+1][(c0>>1)+1] = __floats2half2_rn(o.z, o.w);
        }
    }
    __syncthreads();
    {
        int c0 = (tid & 15)*4, t0 = (tid >> 4)*2;
        ull a00=0ull,a01=0ull,a10=0ull,a11=0ull;
        #pragma unroll 4
        for (int fp = 0; fp < 128; fp++) {
            float2 h0f = __half22float2(sg2[t0][fp]);
            float2 h1f = __half22float2(sg2[t0+1][fp]);
            int f = fp*2;
            float4 wA = *(const float4*)(w2 + f*64 + c0);
            float4 wB = *(const float4*)(w2 + (f+1)*64 + c0);
            ull wloA = pk2(wA.x,wA.y), whiA = pk2(wA.z,wA.w);
            ull wloB = pk2(wB.x,wB.y), whiB = pk2(wB.z,wB.w);
            ull h00 = pk2(h0f.x,h0f.x), h01 = pk2(h0f.y,h0f.y);
            ull h10 = pk2(h1f.x,h1f.x), h11 = pk2(h1f.y,h1f.y);
            a00 = ffma2(h00, wloA, a00); a01 = ffma2(h00, whiA, a01);
            a10 = ffma2(h10, wloA, a10); a11 = ffma2(h10, whiA, a11);
            a00 = ffma2(h01, wloB, a00); a01 = ffma2(h01, whiB, a01);
            a10 = ffma2(h11, wloB, a10); a11 = ffma2(h11, whiB, a11);
        }
        float4 bv = *(const float4*)(b2 + c0);
        float2 p0 = up2(a00), p1 = up2(a01), p2 = up2(a10), p3 = up2(a11);
        float4 r = *(float4*)(&st[t0][c0]);
        r.x += p0.x+bv.x; r.y += p0.y+bv.y; r.z += p1.x+bv.z; r.w += p1.y+bv.w;
        *(float4*)(g_tokens + (size_t)(n0+t0)*64 + c0) = r;
        float4 r2 = *(float4*)(&st[t0+1][c0]);
        r2.x += p2.x+bv.x; r2.y += p2.y+bv.y; r2.z += p3.x+bv.z; r2.w += p3.y+bv.w;
        *(float4*)(g_tokens + (size_t)(n0+t0+1)*64 + c0) = r2;
    }
    #undef SA_
    #undef SHT_
}

// fused readout: mean-over-T + 5x5 conv (pad 2) + spatial sum via clipped tap sums
__global__ void k_read(const float* __restrict__ x, const float* __restrict__ tw) {
    int idx = blockIdx.x*256 + threadIdx.x;
    int hw = idx % HW_;
    int t2 = idx / HW_;
    int c = t2 % (D_+1), b = t2 / (D_+1);
    float v;
    if (c < D_) {
        float acc = 0.f;
        #pragma unroll
        for (int t = 0; t < T_; t++)
            acc += g_tokens[(size_t)b*S_*64 + (size_t)c*THW_ + t*HW_ + hw];
        v = acc*(1.f/T_);
    } else {
        v = x[((size_t)b*3 + 2)*THW_ + hw];
    }
    int y = hw / WW_, xx = hw % WW_;
    int kylo = max(0, y-45), kyhi = min(4, y+2);
    int kxlo = max(0, xx-45), kxhi = min(4, xx+2);
    float w = 0.f;
    for (int ky = kylo; ky <= kyhi; ky++)
        for (int kx = kxlo; kx <= kxhi; kx++)
            w += tw[c*25 + ky*5 + kx];
    float contrib = v*w;
    __shared__ float red[256];
    red[threadIdx.x] = contrib; __syncthreads();
    #pragma unroll
    for (int o = 128; o; o >>= 1) {
        if (threadIdx.x < o) red[threadIdx.x] += red[threadIdx.x + o];
        __syncthreads();
    }
    if (threadIdx.x == 0) atomicAdd(&g_accum[b], red[0]);
}

__global__ void k_final(const float* __restrict__ tb, const float* __restrict__ rw,
                        const float* __restrict__ rb, float* __restrict__ out) {
    int b = threadIdx.x;
    if (b < B_) out[b] = (g_accum[b]*(1.f/HW_) + tb[0])*rw[0] + rb[0];
}

extern "C" void kernel_launch(void* const* d_in, const int* in_sizes, int n_in,
                              void* d_out, int out_size) {
    const float* x    = (const float*)d_in[0];
    const float* prw  = (const float*)d_in[1];
    const float* prb  = (const float*)d_in[2];
    const float* ln1g = (const float*)d_in[3];
    const float* ln1b = (const float*)d_in[4];
    const float* wq   = (const float*)d_in[5];
    const float* wk   = (const float*)d_in[6];
    const float* wv   = (const float*)d_in[7];
    const float* wo   = (const float*)d_in[8];
    const float* bo   = (const float*)d_in[9];
    const float* proj = (const float*)d_in[10];
    const float* ln2g = (const float*)d_in[11];
    const float* ln2b = (const float*)d_in[12];
    const float* w1   = (const float*)d_in[13];
    const float* b1   = (const float*)d_in[14];
    const float* w2   = (const float*)d_in[15];
    const float* b2   = (const float*)d_in[16];
    const float* tw   = (const float*)d_in[17];
    const float* tb   = (const float*)d_in[18];
    const float* rw   = (const float*)d_in[19];
    const float* rb   = (const float*)d_in[20];
    float* out = (float*)d_out;

    k_init<<<1, 32>>>();
    k_qkv<<<N_/32, 256>>>(x, prw, prb, ln1g, ln1b, wq, wk, wv, proj);
    k_chunksum<<<NCH_/2, 256>>>();
    k_scanA<<<B_*NH_*NSEG_, CSZ_/4>>>();
    k_scanC<<<B_*NH_*NSEG_, CSZ_/4>>>();
    k_intra<<<NCH_, 256>>>();
    k_post<<<N_/32, 256>>>(wo, bo, ln2g, ln2b, w1, b1, w2, b2);
    k_read<<<(B_*(D_+1)*HW_)/256, 256>>>(x, tw);
    k_final<<<1, 32>>>(tb, rw, rb, out);
}